// round 17
// baseline (speedup 1.0000x reference)
#include <cuda_runtime.h>
#include <cstdint>

#define D 128
#define MAXN 100000
#define MAXE 600000
#define NEG_SLOPE 0.01f
#define FULL 0xFFFFFFFFu

// ---------------- scratch (static device globals; no allocation) ----------------
// g_cnt invariant: starts zero (static init); k_prep counts up, k_scatter
// atomicSub's every element back to exactly 0 -> self-restoring across replays.
static __device__ float g_vl[3][D];
static __device__ float g_vr[3][D];
static __device__ float g_M[D * D];                    // Wq^T @ Wk
static __device__ float g_sl[3][MAXN];
static __device__ float g_sr[3][MAXN];
static __device__ int   g_cnt[3][MAXN];                // counts -> consumed as cursors
static __device__ int   g_off[3][MAXN + 1];
static __device__ int2  g_epack[3][MAXE];              // (src, exp-score bits), by dst

__device__ __forceinline__ unsigned long long pack2(float lo, float hi) {
    unsigned long long r;
    asm("mov.b64 %0, {%1, %2};" : "=l"(r) : "f"(lo), "f"(hi));
    return r;
}
__device__ __forceinline__ float2 unpack2(unsigned long long v) {
    float2 r;
    asm("mov.b64 {%0, %1}, %2;" : "=f"(r.x), "=f"(r.y) : "l"(v));
    return r;
}
#define FMA2(d, a, b, c) \
    asm("fma.rn.f32x2 %0, %1, %2, %3;" : "=l"(d) : "l"(a), "l"(b), "l"(c))

// ---------------- K1: fused prep (vec | M | counts), 128-thread blocks ----------------
__global__ void k_prep(const float* __restrict__ W1_0, const float* __restrict__ W1_1,
                       const float* __restrict__ W1_2, const float* __restrict__ w2_0,
                       const float* __restrict__ w2_1, const float* __restrict__ w2_2,
                       const float* __restrict__ Wq, const float* __restrict__ Wk,
                       const int* __restrict__ d0, const int* __restrict__ d1,
                       const int* __restrict__ d2, int e0, int e1, int e2, int ebpr) {
    int b = blockIdx.x;
    if (b < 6) {
        int r = b >> 1;
        int half = b & 1;
        const float* W1 = (r == 0) ? W1_0 : (r == 1) ? W1_1 : W1_2;
        const float* w2 = ((r == 0) ? w2_0 : (r == 1) ? w2_1 : w2_2) + half * D;
        int j = threadIdx.x;
        float s = 0.f;
#pragma unroll 8
        for (int i = 0; i < D; i++) s += W1[i * D + j] * w2[i];
        if (half) g_vr[r][j] = s; else g_vl[r][j] = s;
    } else if (b < 134) {
        int dd = b - 6;
        int j = threadIdx.x;
        float s = 0.f;
#pragma unroll 8
        for (int e = 0; e < D; e++) s += Wq[e * D + dd] * Wk[e * D + j];
        g_M[dd * D + j] = s;
    } else {
        int cb = b - 134;
        int r = cb / ebpr;
        int t = (cb - r * ebpr) * 128 + threadIdx.x;
        const int* dst = (r == 0) ? d0 : (r == 1) ? d1 : d2;
        int E = (r == 0) ? e0 : (r == 1) ? e1 : e2;
        if (t >= E) return;
        atomicAdd(&g_cnt[r][dst[t]], 1);
    }
}

// ---------------- K2: fused scores (warp/node) | CSR scan (last 3 blocks) ----------------
__global__ void __launch_bounds__(256)
k_scores_scan(const float* __restrict__ Nmat, int n, int nbs) {
    int b = blockIdx.x;
    if (b < nbs) {
        int w = (b * 256 + threadIdx.x) >> 5;
        int lane = threadIdx.x & 31;
        if (w >= n) return;
        float4 x = ((const float4*)(Nmat + (size_t)w * D))[lane];
        float p0, p1, p2, p3, p4, p5;
        {
            float4 a = ((const float4*)g_vl[0])[lane];
            float4 c = ((const float4*)g_vr[0])[lane];
            p0 = x.x * a.x + x.y * a.y + x.z * a.z + x.w * a.w;
            p1 = x.x * c.x + x.y * c.y + x.z * c.z + x.w * c.w;
        }
        {
            float4 a = ((const float4*)g_vl[1])[lane];
            float4 c = ((const float4*)g_vr[1])[lane];
            p2 = x.x * a.x + x.y * a.y + x.z * a.z + x.w * a.w;
            p3 = x.x * c.x + x.y * c.y + x.z * c.z + x.w * c.w;
        }
        {
            float4 a = ((const float4*)g_vl[2])[lane];
            float4 c = ((const float4*)g_vr[2])[lane];
            p4 = x.x * a.x + x.y * a.y + x.z * a.z + x.w * a.w;
            p5 = x.x * c.x + x.y * c.y + x.z * c.z + x.w * c.w;
        }
#pragma unroll
        for (int o = 16; o; o >>= 1) {
            p0 += __shfl_xor_sync(FULL, p0, o);
            p1 += __shfl_xor_sync(FULL, p1, o);
            p2 += __shfl_xor_sync(FULL, p2, o);
            p3 += __shfl_xor_sync(FULL, p3, o);
            p4 += __shfl_xor_sync(FULL, p4, o);
            p5 += __shfl_xor_sync(FULL, p5, o);
        }
        if (lane == 0) {
            g_sl[0][w] = p0; g_sr[0][w] = p1;
            g_sl[1][w] = p2; g_sr[1][w] = p3;
            g_sl[2][w] = p4; g_sr[2][w] = p5;
        }
    } else {
        int r = b - nbs;
        __shared__ int warpsum[8];
        int tid = threadIdx.x;
        int lane = tid & 31, wid = tid >> 5;
        int chunk = (n + 255) >> 8;
        int beg = tid * chunk;
        int end = beg + chunk; if (end > n) end = n;
        if (beg > n) beg = n;
        int loc = 0;
        for (int i = beg; i < end; i++) loc += g_cnt[r][i];
        int v = loc;
#pragma unroll
        for (int o = 1; o < 32; o <<= 1) {
            int t = __shfl_up_sync(FULL, v, o);
            if (lane >= o) v += t;
        }
        if (lane == 31) warpsum[wid] = v;
        __syncthreads();
        if (wid == 0 && lane < 8) {
            int s = warpsum[lane];
#pragma unroll
            for (int o = 1; o < 8; o <<= 1) {
                int t = __shfl_up_sync(0xFFu, s, o);
                if (lane >= o) s += t;
            }
            warpsum[lane] = s;
        }
        __syncthreads();
        int excl = v - loc + (wid ? warpsum[wid - 1] : 0);
        int run = excl;
        for (int i = beg; i < end; i++) {
            g_off[r][i] = run;
            run += g_cnt[r][i];
        }
        if (end == n) g_off[r][n] = run;
    }
}

// ---------------- K3: scatter edges (counts consumed as cursors -> back to 0) ----------------
__global__ void k_scatter(const int* __restrict__ s0, const int* __restrict__ s1,
                          const int* __restrict__ s2, const int* __restrict__ d0,
                          const int* __restrict__ d1, const int* __restrict__ d2,
                          int e0, int e1, int e2) {
    int r = blockIdx.y;
    const int* src = (r == 0) ? s0 : (r == 1) ? s1 : s2;
    const int* dst = (r == 0) ? d0 : (r == 1) ? d1 : d2;
    int E = (r == 0) ? e0 : (r == 1) ? e1 : e2;
    int t = blockIdx.x * blockDim.x + threadIdx.x;
    if (t >= E) return;
    int s = src[t];
    int d = dst[t];
    float ev = g_sl[r][s] + g_sr[r][d];
    ev = (ev >= 0.f) ? ev : NEG_SLOPE * ev;
    float ex = __expf(ev);
    int pos = g_off[r][d] + atomicSub(&g_cnt[r][d], 1) - 1;
    g_epack[r][pos] = make_int2(s, __float_as_int(ex));
}

// ---------------- K4: FUSED aggregation + attention (warp per 8 nodes) ----------------
// h never touches gmem: staged per-warp in smem (exactly 48KB static -> 4 blocks/SM).
#define AW 4
__global__ void __launch_bounds__(128)
k_aggattn(const float* __restrict__ Nmat, float* __restrict__ out,
          int n, const int* __restrict__ tptr) {
    __shared__ float h_sm[AW][8][3][D];   // 4*8*3*128*4 = 49152 B
    int wlocal = threadIdx.x >> 5;
    int gw = (blockIdx.x * blockDim.x + threadIdx.x) >> 5;
    int lane = threadIdx.x & 31;
    int node0 = gw * 8;
    if (node0 >= n) return;

    int t = tptr ? tptr[0] : 0;
    t = (t < 0) ? 0 : ((t > 2) ? 2 : t);

    const float4* N4 = (const float4*)Nmat;

    // ---- Phase A: aggregation for 8 nodes x 3 relations -> h_sm ----
    for (int q = 0; q < 8; q++) {
        int node = node0 + q;
        if (node >= n) {
            // zero-fill so Phase B math stays finite (results unused)
#pragma unroll
            for (int r = 0; r < 3; r++)
                *(float4*)&h_sm[wlocal][q][r][lane * 4] = make_float4(0.f, 0.f, 0.f, 0.f);
            continue;
        }
#pragma unroll
        for (int r = 0; r < 3; r++) {
            int beg = g_off[r][node];
            int end = g_off[r][node + 1];
            const int2* ep = g_epack[r];
            float4 acc = make_float4(0.f, 0.f, 0.f, 0.f);
            float den = 0.f;
            for (int base = beg; base < end; base += 32) {
                int cnt = end - base; if (cnt > 32) cnt = 32;
                int2 evp = make_int2(0, 0);
                if (lane < cnt) evp = __ldcs(&ep[base + lane]);
#pragma unroll 4
                for (int j = 0; j < cnt; j++) {
                    int s = __shfl_sync(FULL, evp.x, j);
                    float ex = __int_as_float(__shfl_sync(FULL, evp.y, j));
                    float4 nv = N4[(size_t)s * 32 + lane];
                    acc.x += ex * nv.x; acc.y += ex * nv.y;
                    acc.z += ex * nv.z; acc.w += ex * nv.w;
                    den += ex;
                }
            }
            float iv = (den > 0.f) ? (1.f / den) : 0.f;
            *(float4*)&h_sm[wlocal][q][r][lane * 4] =
                make_float4(acc.x * iv, acc.y * iv, acc.z * iv, acc.w * iv);
        }
    }
    __syncwarp();

    // ---- Phase B: u[q] = ht[q] @ M  (M register-amortized over 8 nodes) ----
    unsigned long long u01[8], u23[8];
    unsigned long long z = pack2(0.f, 0.f);
#pragma unroll
    for (int q = 0; q < 8; q++) { u01[q] = z; u23[q] = z; }

    const longlong2* M2 = (const longlong2*)g_M;
#pragma unroll 2
    for (int s = 0; s < 32; s++) {
        longlong2 ml0 = M2[(size_t)(s * 4 + 0) * 32 + lane];
        longlong2 ml1 = M2[(size_t)(s * 4 + 1) * 32 + lane];
        longlong2 ml2 = M2[(size_t)(s * 4 + 2) * 32 + lane];
        longlong2 ml3 = M2[(size_t)(s * 4 + 3) * 32 + lane];
#pragma unroll
        for (int q = 0; q < 8; q++) {
            const float* bt = &h_sm[wlocal][q][t][s * 4];
            float b0 = bt[0], b1 = bt[1], b2 = bt[2], b3 = bt[3];  // uniform -> LDS broadcast
            unsigned long long bb;
            bb = pack2(b0, b0);
            FMA2(u01[q], (unsigned long long)ml0.x, bb, u01[q]);
            FMA2(u23[q], (unsigned long long)ml0.y, bb, u23[q]);
            bb = pack2(b1, b1);
            FMA2(u01[q], (unsigned long long)ml1.x, bb, u01[q]);
            FMA2(u23[q], (unsigned long long)ml1.y, bb, u23[q]);
            bb = pack2(b2, b2);
            FMA2(u01[q], (unsigned long long)ml2.x, bb, u01[q]);
            FMA2(u23[q], (unsigned long long)ml2.y, bb, u23[q]);
            bb = pack2(b3, b3);
            FMA2(u01[q], (unsigned long long)ml3.x, bb, u01[q]);
            FMA2(u23[q], (unsigned long long)ml3.y, bb, u23[q]);
        }
    }

    // ---- Phase C: per-node scores, softmax over 3, combine, store ----
    const float sc = 0.0883883476483184f;  // 1/sqrt(128)
#pragma unroll
    for (int q = 0; q < 8; q++) {
        int node = node0 + q;
        if (node >= n) break;
        float2 ua = unpack2(u01[q]);
        float2 ub = unpack2(u23[q]);
        float4 h0 = *(const float4*)&h_sm[wlocal][q][0][lane * 4];
        float4 h1 = *(const float4*)&h_sm[wlocal][q][1][lane * 4];
        float4 h2 = *(const float4*)&h_sm[wlocal][q][2][lane * 4];
        float e0 = ua.x * h0.x + ua.y * h0.y + ub.x * h0.z + ub.y * h0.w;
        float e1 = ua.x * h1.x + ua.y * h1.y + ub.x * h1.z + ub.y * h1.w;
        float e2 = ua.x * h2.x + ua.y * h2.y + ub.x * h2.z + ub.y * h2.w;
#pragma unroll
        for (int o = 16; o; o >>= 1) {
            e0 += __shfl_xor_sync(FULL, e0, o);
            e1 += __shfl_xor_sync(FULL, e1, o);
            e2 += __shfl_xor_sync(FULL, e2, o);
        }
        e0 *= sc; e1 *= sc; e2 *= sc;
        float mx = fmaxf(e0, fmaxf(e1, e2));
        float a0 = __expf(e0 - mx), a1 = __expf(e1 - mx), a2 = __expf(e2 - mx);
        float is = 1.f / (a0 + a1 + a2);
        a0 *= is; a1 *= is; a2 *= is;

        float4 o4;
        o4.x = a0 * h0.x + a1 * h1.x + a2 * h2.x;
        o4.y = a0 * h0.y + a1 * h1.y + a2 * h2.y;
        o4.z = a0 * h0.z + a1 * h1.z + a2 * h2.z;
        o4.w = a0 * h0.w + a1 * h1.w + a2 * h2.w;
        __stcs((float4*)(out + (size_t)node * D + lane * 4), o4);
    }
}

// ---------------- launcher ----------------
extern "C" void kernel_launch(void* const* d_in, const int* in_sizes, int n_in,
                              void* d_out, int out_size) {
    const float* Nmat = (const float*)d_in[0];
    const float* W1_0 = (const float*)d_in[1];
    const float* W1_1 = (const float*)d_in[2];
    const float* W1_2 = (const float*)d_in[3];
    const float* w2_0 = (const float*)d_in[4];
    const float* w2_1 = (const float*)d_in[5];
    const float* w2_2 = (const float*)d_in[6];
    const float* Wq   = (const float*)d_in[7];
    const float* Wk   = (const float*)d_in[8];
    const int* s0 = (const int*)d_in[10];
    const int* d0 = (const int*)d_in[11];
    const int* s1 = (const int*)d_in[12];
    const int* d1 = (const int*)d_in[13];
    const int* s2 = (const int*)d_in[14];
    const int* d2 = (const int*)d_in[15];
    const int* tptr = (n_in > 16) ? (const int*)d_in[16] : nullptr;

    int n = in_sizes[0] / D;
    if (n > MAXN) n = MAXN;
    int e0 = in_sizes[10]; if (e0 > MAXE) e0 = MAXE;
    int e1 = in_sizes[12]; if (e1 > MAXE) e1 = MAXE;
    int e2 = in_sizes[14]; if (e2 > MAXE) e2 = MAXE;
    int emax = e0 > e1 ? (e0 > e2 ? e0 : e2) : (e1 > e2 ? e1 : e2);

    // 1: prep (vec | M | counts)  -- g_cnt enters zero (static init + self-restore)
    int ebpr = (emax + 127) / 128;
    k_prep<<<134 + 3 * ebpr, 128>>>(W1_0, W1_1, W1_2, w2_0, w2_1, w2_2, Wq, Wk,
                                    d0, d1, d2, e0, e1, e2, ebpr);

    // 2: scores | scan
    int nbs = (n + 7) / 8;
    k_scores_scan<<<nbs + 3, 256>>>(Nmat, n, nbs);

    // 3: scatter (restores g_cnt to zero)
    dim3 gc((emax + 255) / 256, 3);
    k_scatter<<<gc, 256>>>(s0, s1, s2, d0, d1, d2, e0, e1, e2);

    // 4: fused aggregation + attention  (<- profiled slot)
    //    4 warps x 8 nodes = 32 nodes per 128-thread block
    int nb = (n + 31) / 32;
    k_aggattn<<<nb, 128>>>(Nmat, (float*)d_out, n, tptr);
}